// round 5
// baseline (speedup 1.0000x reference)
#include <cuda_runtime.h>
#include <cstdint>

// Per-row nonlinear scan, w[k+1] = w[k] + a/w[k] - b*x[k], 32768 rows x 1024.
// One thread per row; 32x32 smem transpose tiles (pad +1 -> conflict-free).
//
// Structure = ROUND 2 exactly (best measured: 57.3us ncu, rel_err 0.0).
// Single change: a/w computed with the hand-written IEEE-div FAST PATH
// (identical 6-op Markstein sequence ptxas emits for div.rn.f32) WITHOUT the
// FCHK + BSSY/BSYNC slow-path scaffolding that costs ~40-60 cyc per step.
// On normal operands this is bitwise-identical to `a / w`.
// (Bare rcp.approx is NOT acceptable: round 3 showed rel_err 2.05 -- the
// recurrence is chaotic on rows where w nears 0.)

#define N_COLS 1024
#define WARPS_PER_BLOCK 4
#define TILE 32

// Correctly-rounded a/w for normal-range operands: the div.rn.f32 fast path.
__device__ __forceinline__ float div_fast_rn(float a, float w) {
    float r;
    asm("rcp.approx.f32 %0, %1;" : "=f"(r) : "f"(w));   // MUFU.RCP
    float e   = __fmaf_rn(-w, r, 1.0f);                 // residual of rcp
    r         = __fmaf_rn(e, r, r);                     // refined reciprocal
    float q0  = __fmul_rn(a, r);                        // initial quotient
    float rem = __fmaf_rn(-w, q0, a);                   // exact remainder (FMA)
    return      __fmaf_rn(rem, r, q0);                  // correctly-rounded q
}

__global__ __launch_bounds__(WARPS_PER_BLOCK * 32)
void DDK_77644418777662_kernel(const float* __restrict__ x,
                               const float* __restrict__ alpha,
                               const float* __restrict__ beta,
                               float* __restrict__ out,
                               int rows) {
    // one 32x33 tile per warp (disjoint regions -> __syncwarp suffices)
    __shared__ float sh[WARPS_PER_BLOCK][TILE][TILE + 1];

    const int warp = threadIdx.x >> 5;
    const int lane = threadIdx.x & 31;
    const int rowBase = (blockIdx.x * WARPS_PER_BLOCK + warp) * TILE;
    if (rowBase >= rows) return;

    const float a = __ldg(alpha);
    const float b = __ldg(beta);

    const float* xrow = x + (size_t)rowBase * N_COLS;
    float* orow       = out + (size_t)rowBase * N_COLS;

    // cooperative tile indexing: 32 lanes = 4 rows x 8 float4-chunks per pass
    const int tr = lane >> 3;   // 0..3 row offset within 4-row group
    const int tc = lane & 7;    // 0..7 float4 index within row

    float4 pf[8];

    // ---- prologue: load tile 0 into registers, commit to smem ----
    #pragma unroll
    for (int g = 0; g < 8; g++)
        pf[g] = *(const float4*)(xrow + (size_t)(g * 4 + tr) * N_COLS + tc * 4);
    #pragma unroll
    for (int g = 0; g < 8; g++) {
        const int r = g * 4 + tr;
        sh[warp][r][tc * 4 + 0] = pf[g].x;
        sh[warp][r][tc * 4 + 1] = pf[g].y;
        sh[warp][r][tc * 4 + 2] = pf[g].z;
        sh[warp][r][tc * 4 + 3] = pf[g].w;
    }
    __syncwarp();

    float w = 1.0f;

    for (int c0 = 0; c0 < N_COLS; c0 += TILE) {
        const int next = c0 + TILE;

        // ---- issue next tile's loads: 8 independent LDG.128 fly during compute ----
        if (next < N_COLS) {
            #pragma unroll
            for (int g = 0; g < 8; g++)
                pf[g] = *(const float4*)(xrow + (size_t)(g * 4 + tr) * N_COLS
                                         + next + tc * 4);
        }

        // ---- 32 sequential recurrence steps (the dependent chain) ----
        // out[k] = w (pre-update), overwrite smem in place.
        // Last global step's update is computed but never stored (harmless).
        #pragma unroll
        for (int j = 0; j < TILE; j++) {
            const float xv = sh[warp][lane][j];
            sh[warp][lane][j] = w;
            // EXACT semantics of: w = w + a / w - b * xv;
            const float q = div_fast_rn(a, w);
            w = (w + q) - b * xv;
        }
        __syncwarp();

        // ---- coalesced store of this tile's outputs ----
        #pragma unroll
        for (int g = 0; g < 8; g++) {
            const int r = g * 4 + tr;
            float4 v;
            v.x = sh[warp][r][tc * 4 + 0];
            v.y = sh[warp][r][tc * 4 + 1];
            v.z = sh[warp][r][tc * 4 + 2];
            v.w = sh[warp][r][tc * 4 + 3];
            *(float4*)(orow + (size_t)r * N_COLS + c0 + tc * 4) = v;
        }
        __syncwarp();

        // ---- commit prefetched registers to smem for the next iteration ----
        if (next < N_COLS) {
            #pragma unroll
            for (int g = 0; g < 8; g++) {
                const int r = g * 4 + tr;
                sh[warp][r][tc * 4 + 0] = pf[g].x;
                sh[warp][r][tc * 4 + 1] = pf[g].y;
                sh[warp][r][tc * 4 + 2] = pf[g].z;
                sh[warp][r][tc * 4 + 3] = pf[g].w;
            }
            __syncwarp();
        }
    }
}

extern "C" void kernel_launch(void* const* d_in, const int* in_sizes, int n_in,
                              void* d_out, int out_size) {
    const float* x     = (const float*)d_in[0];
    const float* alpha = (const float*)d_in[1];
    const float* beta  = (const float*)d_in[2];
    float* out         = (float*)d_out;

    const int rows = out_size / N_COLS;                 // 32768
    const int rowsPerBlock = WARPS_PER_BLOCK * TILE;    // 128
    const int blocks = (rows + rowsPerBlock - 1) / rowsPerBlock;  // 256

    DDK_77644418777662_kernel<<<blocks, WARPS_PER_BLOCK * 32>>>(x, alpha, beta, out, rows);
}

// round 6
// speedup vs baseline: 1.2229x; 1.2229x over previous
#include <cuda_runtime.h>
#include <cstdint>

// Per-row nonlinear scan, w[k+1] = w[k] + a/w[k] - b*x[k], 32768 rows x 1024.
// One thread per row; 32x32 smem transpose tiles (pad +1 -> conflict-free).
//
// ARITHMETIC (FROZEN, bitwise-matches reference; rel_err 0.0 in R1/R2/R5):
//     w = w + a / w - b * xv;          // IEEE div, default rounding
// Do NOT reassociate, do NOT use rcp.approx (R3: rel_err 2.05, chaotic map),
// do NOT hand-expand the division (R5: slower than ptxas div.rn).
//
// Round 6 = Round 2 (best: 57.3us) + ONE change: double-buffered smem tile,
// with tile t-1's output stores (8x LDS.128+STG.128) FUSED into tile t's
// 32-step compute loop so they issue in the divide chain's stall shadow.
// This removes the fully-exposed serial store block between compute phases
// and keeps DRAM store traffic flowing during compute.

#define N_COLS 1024
#define WPB 4
#define TILE 32
#define NT (N_COLS / TILE)   // 32

__global__ __launch_bounds__(WPB * 32)
void DDK_77644418777662_kernel(const float* __restrict__ x,
                               const float* __restrict__ alpha,
                               const float* __restrict__ beta,
                               float* __restrict__ out,
                               int rows) {
    // two 32x33 tiles per warp, alternating roles (disjoint per warp)
    __shared__ float sh[2][WPB][TILE][TILE + 1];

    const int warp = threadIdx.x >> 5;
    const int lane = threadIdx.x & 31;
    const int rowBase = (blockIdx.x * WPB + warp) * TILE;
    if (rowBase >= rows) return;

    const float a = __ldg(alpha);
    const float b = __ldg(beta);

    const float* xrow = x + (size_t)rowBase * N_COLS;
    float* orow       = out + (size_t)rowBase * N_COLS;

    // cooperative tile indexing: 32 lanes = 4 rows x 8 float4-chunks
    const int tr = lane >> 3;   // 0..3
    const int tc = lane & 7;    // 0..7

    float4 pf[8];

    // ---- prologue: tile 0 -> sh[0] ----
    #pragma unroll
    for (int g = 0; g < 8; g++)
        pf[g] = *(const float4*)(xrow + (size_t)(g * 4 + tr) * N_COLS + tc * 4);
    #pragma unroll
    for (int g = 0; g < 8; g++) {
        const int r = g * 4 + tr;
        sh[0][warp][r][tc * 4 + 0] = pf[g].x;
        sh[0][warp][r][tc * 4 + 1] = pf[g].y;
        sh[0][warp][r][tc * 4 + 2] = pf[g].z;
        sh[0][warp][r][tc * 4 + 3] = pf[g].w;
    }
    __syncwarp();

    float w = 1.0f;

    for (int t = 0; t < NT; t++) {
        const int cur = t & 1;
        const int prv = cur ^ 1;

        // ---- issue tile t+1's loads (fly during the compute chain) ----
        if (t + 1 < NT) {
            const int c0 = (t + 1) * TILE;
            #pragma unroll
            for (int g = 0; g < 8; g++)
                pf[g] = *(const float4*)(xrow + (size_t)(g * 4 + tr) * N_COLS
                                         + c0 + tc * 4);
        }

        // ---- 32 sequential steps; tile t-1's stores fused into the chain ----
        // sh[cur] holds tile t inputs, overwritten in place with outputs.
        // sh[prv] holds tile t-1 outputs; one LDS.128+STG.128 every 4 steps.
        const int cprev = (t - 1) * TILE;
        #pragma unroll
        for (int j = 0; j < TILE; j++) {
            const float xv = sh[cur][warp][lane][j];
            sh[cur][warp][lane][j] = w;
            w = w + a / w - b * xv;        // FROZEN expression
            if ((j & 3) == 0 && t >= 1) {
                const int g = j >> 2;      // 0..7
                const int r = g * 4 + tr;
                float4 v;
                v.x = sh[prv][warp][r][tc * 4 + 0];
                v.y = sh[prv][warp][r][tc * 4 + 1];
                v.z = sh[prv][warp][r][tc * 4 + 2];
                v.w = sh[prv][warp][r][tc * 4 + 3];
                *(float4*)(orow + (size_t)r * N_COLS + cprev + tc * 4) = v;
            }
        }
        __syncwarp();   // all lanes done reading sh[prv] + writing sh[cur]

        // ---- commit tile t+1 inputs into the buffer just freed (prv) ----
        if (t + 1 < NT) {
            #pragma unroll
            for (int g = 0; g < 8; g++) {
                const int r = g * 4 + tr;
                sh[prv][warp][r][tc * 4 + 0] = pf[g].x;
                sh[prv][warp][r][tc * 4 + 1] = pf[g].y;
                sh[prv][warp][r][tc * 4 + 2] = pf[g].z;
                sh[prv][warp][r][tc * 4 + 3] = pf[g].w;
            }
            __syncwarp();
        }
    }

    // ---- epilogue: store the last tile's outputs ----
    {
        const int buf = (NT - 1) & 1;
        const int c0 = (NT - 1) * TILE;
        #pragma unroll
        for (int g = 0; g < 8; g++) {
            const int r = g * 4 + tr;
            float4 v;
            v.x = sh[buf][warp][r][tc * 4 + 0];
            v.y = sh[buf][warp][r][tc * 4 + 1];
            v.z = sh[buf][warp][r][tc * 4 + 2];
            v.w = sh[buf][warp][r][tc * 4 + 3];
            *(float4*)(orow + (size_t)r * N_COLS + c0 + tc * 4) = v;
        }
    }
}

extern "C" void kernel_launch(void* const* d_in, const int* in_sizes, int n_in,
                              void* d_out, int out_size) {
    const float* x     = (const float*)d_in[0];
    const float* alpha = (const float*)d_in[1];
    const float* beta  = (const float*)d_in[2];
    float* out         = (float*)d_out;

    const int rows = out_size / N_COLS;                 // 32768
    const int rowsPerBlock = WPB * TILE;                // 128
    const int blocks = (rows + rowsPerBlock - 1) / rowsPerBlock;  // 256

    DDK_77644418777662_kernel<<<blocks, WPB * 32>>>(x, alpha, beta, out, rows);
}